// round 1
// baseline (speedup 1.0000x reference)
#include <cuda_runtime.h>

#define B_  1024
#define N_  128
#define H_  128
#define FE_ 8
#define G3_ 384      // 3*H
#define KX_ 136      // H+FE

// device scratch (no cudaMalloc allowed)
__device__ __align__(16) float g_hs[B_ * H_];        // per-batch sum of h over N
__device__ __align__(16) float g_bias[B_ * G3_];     // per-batch gate bias (message part + b_ih [+ b_hh])
__device__ __align__(16) float g_WT[H_ * G3_];       // WT[k][g] = W_hh[g][k]

// ---------------- K0: transpose W_hh [384,128] -> WT [128,384] ----------------
__global__ void k_transpose(const float* __restrict__ Whh) {
    int idx = blockIdx.x * 256 + threadIdx.x;
    if (idx < G3_ * H_) {
        int g = idx / H_, k = idx % H_;
        g_WT[k * G3_ + g] = Whh[idx];
    }
}

// ---------------- K1: hs[b,k] = sum_n h[b,n,k] ----------------
__global__ void k_rowsum(const float* __restrict__ h) {
    int b = blockIdx.x;
    int k = threadIdx.x;
    const float* p = h + (size_t)b * N_ * H_ + k;
    float s0 = 0.f, s1 = 0.f, s2 = 0.f, s3 = 0.f;
    #pragma unroll 8
    for (int n = 0; n < N_; n += 4) {
        s0 += p[(n + 0) * H_];
        s1 += p[(n + 1) * H_];
        s2 += p[(n + 2) * H_];
        s3 += p[(n + 3) * H_];
    }
    g_hs[b * H_ + k] = (s0 + s1) + (s2 + s3);
}

// ---------------- K2: per-batch message + gate bias ----------------
// message[b,k] = tanh(hs[b]·Wm[k,:] + N*bm[k])
// bias[b,g]    = message[b]·W_ih[g,0:128] + b_ih[g] + (g<256 ? b_hh[g] : 0)
__global__ void k_bias(const float* __restrict__ Wm, const float* __restrict__ bm,
                       const float* __restrict__ Wih, const float* __restrict__ bih,
                       const float* __restrict__ bhh) {
    __shared__ float hsS[H_];
    __shared__ float msgS[H_];
    int b = blockIdx.x;
    int k = threadIdx.x;

    hsS[k] = g_hs[b * H_ + k];
    __syncthreads();

    const float4* wr = (const float4*)(Wm + (size_t)k * H_);
    float d = 0.f;
    #pragma unroll
    for (int j = 0; j < H_ / 4; j++) {
        float4 w = wr[j];
        d += hsS[4 * j + 0] * w.x + hsS[4 * j + 1] * w.y
           + hsS[4 * j + 2] * w.z + hsS[4 * j + 3] * w.w;
    }
    msgS[k] = tanhf(d + (float)N_ * bm[k]);
    __syncthreads();

    #pragma unroll
    for (int q = 0; q < 3; q++) {
        int g = q * H_ + k;
        const float4* wi = (const float4*)(Wih + (size_t)g * KX_);  // 136*4 bytes = 16B-aligned rows
        float d2 = 0.f;
        #pragma unroll
        for (int j = 0; j < H_ / 4; j++) {
            float4 w = wi[j];
            d2 += msgS[4 * j + 0] * w.x + msgS[4 * j + 1] * w.y
                + msgS[4 * j + 2] * w.z + msgS[4 * j + 3] * w.w;
        }
        float bias = d2 + bih[g];
        if (g < 2 * H_) bias += bhh[g];
        g_bias[b * G3_ + g] = bias;
    }
}

// ---------------- K3: fused GEMM (h·W_hh^T, jets·W_ih_jets^T) + GRU epilogue ----------------
// Tile: 32 rows x 384 gate-cols per CTA. 256 threads: (tr=tid/32 -> 4 rows each, tg=tid%32 -> 4 g each).
// smem (floats):
//   As    [32][132]   h tile (padded)
//   jetsS [32][8]
//   WjSt  [8][384]    WjSt[f][g] = W_ih[g][128+f]
//   biasS [384]
//   bhhnS [128]       b_hh[256+g]
//   Ws    [32][388]   K-chunk of WT (padded)
__global__ void __launch_bounds__(256, 2) k_main(
    const float* __restrict__ h, const float* __restrict__ jets,
    const float* __restrict__ Wih, const float* __restrict__ bhh,
    float* __restrict__ out)
{
    extern __shared__ float sm[];
    float* As    = sm;                      // 4224
    float* jetsS = As + 32 * 132;           // 256
    float* WjSt  = jetsS + 32 * 8;          // 3072
    float* biasS = WjSt + 8 * 384;          // 384
    float* bhhnS = biasS + 384;             // 128
    float* Ws    = bhhnS + 128;             // 12416

    const int tid = threadIdx.x;
    const int m0  = blockIdx.x * 32;
    const int b   = m0 >> 7;                // 4 CTAs per batch row-group

    // load h tile -> As (coalesced float4)
    {
        const float4* h4 = (const float4*)(h + (size_t)m0 * H_);
        #pragma unroll
        for (int t = tid; t < 32 * 32; t += 256) {
            int row = t >> 5, c4 = t & 31;
            *(float4*)&As[row * 132 + c4 * 4] = h4[t];
        }
    }
    // jets tile
    {
        const float4* j4 = (const float4*)(jets + (size_t)m0 * FE_);
        if (tid < 64) *(float4*)&jetsS[tid * 4] = j4[tid];
    }
    // WjSt[f][g] = Wih[g][128+f]
    for (int g = tid; g < G3_; g += 256) {
        const float* src = Wih + (size_t)g * KX_ + H_;
        float4 a4 = *(const float4*)(src);
        float4 b4 = *(const float4*)(src + 4);
        WjSt[0 * G3_ + g] = a4.x; WjSt[1 * G3_ + g] = a4.y;
        WjSt[2 * G3_ + g] = a4.z; WjSt[3 * G3_ + g] = a4.w;
        WjSt[4 * G3_ + g] = b4.x; WjSt[5 * G3_ + g] = b4.y;
        WjSt[6 * G3_ + g] = b4.z; WjSt[7 * G3_ + g] = b4.w;
    }
    for (int g = tid; g < G3_; g += 256) biasS[g] = g_bias[b * G3_ + g];
    if (tid < 128) bhhnS[tid] = bhh[256 + tid];

    const int tr = tid >> 5;
    const int tg = tid & 31;
    const int gb = tg * 4;

    float acc0[4][4] = {};   // r:  h·W_hh_r + jets·W_ih_r
    float acc1[4][4] = {};   // z:  h·W_hh_z + jets·W_ih_z
    float acc2[4][4] = {};   // hn: h·W_hh_n
    float accN[4][4] = {};   // in: jets·W_ih_n (message+bias part in biasS)

    for (int kc = 0; kc < H_; kc += 32) {
        __syncthreads();   // protect Ws from overwrite while prior chunk in use
        #pragma unroll
        for (int t = tid; t < 32 * 96; t += 256) {   // 32 k-rows x 96 float4
            int kk = t / 96, c4 = t % 96;
            float4 v = ((const float4*)g_WT)[(kc + kk) * 96 + c4];
            *(float4*)&Ws[kk * 388 + c4 * 4] = v;
        }
        __syncthreads();

        #pragma unroll
        for (int k4 = 0; k4 < 32; k4 += 4) {
            float4 av[4];
            #pragma unroll
            for (int i = 0; i < 4; i++)
                av[i] = *(const float4*)&As[(tr * 4 + i) * 132 + kc + k4];
            #pragma unroll
            for (int kk = 0; kk < 4; kk++) {
                const float4 w0 = *(const float4*)&Ws[(k4 + kk) * 388 + gb];
                const float4 w1 = *(const float4*)&Ws[(k4 + kk) * 388 + 128 + gb];
                const float4 w2 = *(const float4*)&Ws[(k4 + kk) * 388 + 256 + gb];
                #pragma unroll
                for (int i = 0; i < 4; i++) {
                    float a = (kk == 0) ? av[i].x : (kk == 1) ? av[i].y
                            : (kk == 2) ? av[i].z : av[i].w;
                    acc0[i][0] += a * w0.x; acc0[i][1] += a * w0.y;
                    acc0[i][2] += a * w0.z; acc0[i][3] += a * w0.w;
                    acc1[i][0] += a * w1.x; acc1[i][1] += a * w1.y;
                    acc1[i][2] += a * w1.z; acc1[i][3] += a * w1.w;
                    acc2[i][0] += a * w2.x; acc2[i][1] += a * w2.y;
                    acc2[i][2] += a * w2.z; acc2[i][3] += a * w2.w;
                }
            }
        }
    }

    // jets (K=8) contribution
    #pragma unroll
    for (int f = 0; f < 8; f++) {
        const float4 wr = *(const float4*)&WjSt[f * G3_ + gb];
        const float4 wz = *(const float4*)&WjSt[f * G3_ + 128 + gb];
        const float4 wn = *(const float4*)&WjSt[f * G3_ + 256 + gb];
        #pragma unroll
        for (int i = 0; i < 4; i++) {
            float jf = jetsS[(tr * 4 + i) * 8 + f];
            acc0[i][0] += jf * wr.x; acc0[i][1] += jf * wr.y;
            acc0[i][2] += jf * wr.z; acc0[i][3] += jf * wr.w;
            acc1[i][0] += jf * wz.x; acc1[i][1] += jf * wz.y;
            acc1[i][2] += jf * wz.z; acc1[i][3] += jf * wz.w;
            accN[i][0] += jf * wn.x; accN[i][1] += jf * wn.y;
            accN[i][2] += jf * wn.z; accN[i][3] += jf * wn.w;
        }
    }

    // GRU epilogue + store
    const float4 bR4 = *(const float4*)&biasS[gb];
    const float4 bZ4 = *(const float4*)&biasS[128 + gb];
    const float4 bN4 = *(const float4*)&biasS[256 + gb];
    const float4 bH4 = *(const float4*)&bhhnS[gb];
    #pragma unroll
    for (int i = 0; i < 4; i++) {
        int row = tr * 4 + i;
        float4 hv = *(const float4*)&As[row * 132 + gb];
        float o[4];
        #pragma unroll
        for (int j = 0; j < 4; j++) {
            float br = ((const float*)&bR4)[j];
            float bz = ((const float*)&bZ4)[j];
            float bn = ((const float*)&bN4)[j];
            float bh = ((const float*)&bH4)[j];
            float hj = ((const float*)&hv)[j];
            float r = 1.f / (1.f + __expf(-(acc0[i][j] + br)));
            float z = 1.f / (1.f + __expf(-(acc1[i][j] + bz)));
            float n = tanhf(accN[i][j] + bn + r * (acc2[i][j] + bh));
            o[j] = (1.f - z) * n + z * hj;
        }
        *(float4*)(out + (size_t)(m0 + row) * H_ + gb) = make_float4(o[0], o[1], o[2], o[3]);
    }
}

extern "C" void kernel_launch(void* const* d_in, const int* in_sizes, int n_in,
                              void* d_out, int out_size) {
    const float* h    = (const float*)d_in[0];
    const float* jets = (const float*)d_in[1];
    // d_in[2] = mask (unused by reference forward)
    const float* Wm   = (const float*)d_in[3];
    const float* bm   = (const float*)d_in[4];
    const float* Wih  = (const float*)d_in[5];
    const float* Whh  = (const float*)d_in[6];
    const float* bih  = (const float*)d_in[7];
    const float* bhh  = (const float*)d_in[8];
    float* out = (float*)d_out;

    // 80 KB dynamic smem for k_main (idempotent; not a stream op, capture-safe)
    const int smem_bytes = (32 * 132 + 32 * 8 + 8 * 384 + 384 + 128 + 32 * 388) * 4;  // 81920
    cudaFuncSetAttribute(k_main, cudaFuncAttributeMaxDynamicSharedMemorySize, smem_bytes);

    k_transpose<<<(G3_ * H_ + 255) / 256, 256>>>(Whh);
    k_rowsum<<<B_, H_>>>(h);
    k_bias<<<B_, H_>>>(Wm, bm, Wih, bih, bhh);
    k_main<<<(B_ * N_) / 32, 256, smem_bytes>>>(h, jets, Wih, bhh, out);
}